// round 4
// baseline (speedup 1.0000x reference)
#include <cuda_runtime.h>
#include <stdint.h>

#define MAXN 50000
#define MAXE 800000
#define MAXF 216
#define NGRAPHS 64

// ---------------- scratch (static device globals; allocation-free) ----------------
__device__ __align__(16) float g_h[(size_t)MAXN * MAXF];    // GEMM output per layer
__device__ __align__(16) float g_agg[(size_t)MAXN * MAXF];  // aggregated features
__device__ int   g_cnt[MAXN];
__device__ int   g_rowptr[MAXN + 1];
__device__ int   g_cursor[MAXN];
__device__ int   g_csr_src[MAXE];
__device__ float g_csr_w[MAXE];
__device__ float g_dinv[MAXN];
__device__ int   g_starts[NGRAPHS];
__device__ int   g_idx64;   // 1 if index arrays are int64, 0 if int32

// ---------------- index dtype detection ----------------
// edge_index values are uniform in [0, N). If stored as int64 (LE), every odd
// 32-bit word of the buffer is 0. If int32, odd words are random nonzero indices.
__global__ void k_detect(const int* __restrict__ w) {
    if (threadIdx.x == 0 && blockIdx.x == 0) {
        int is64 = 1;
        #pragma unroll 1
        for (int i = 1; i < 128; i += 2)
            if (w[i] != 0) { is64 = 0; break; }
        g_idx64 = is64;
    }
}

__device__ __forceinline__ int idx_at(const void* p, long long i, int is64) {
    return is64 ? (int)((const long long*)p)[i] : ((const int*)p)[i];
}

// ---------------- generic zero ----------------
__global__ void k_zero_f(float* p, size_t n) {
    size_t i = (size_t)blockIdx.x * blockDim.x + threadIdx.x;
    size_t stride = (size_t)gridDim.x * blockDim.x;
    for (; i < n; i += stride) p[i] = 0.f;
}

__global__ void k_zero_i(int* p, int n) {
    int i = blockIdx.x * blockDim.x + threadIdx.x;
    if (i < n) p[i] = 0;
}

// ---------------- CSR build ----------------
__global__ void k_count(const void* __restrict__ ei, int* cnt, int E, int N) {
    int is64 = g_idx64;
    int i = blockIdx.x * blockDim.x + threadIdx.x;
    if (i < E) {
        int d = idx_at(ei, (long long)E + i, is64);
        if (d >= 0 && d < N) atomicAdd(&cnt[d], 1);
    }
}

// single-block scan: rowptr (exclusive), cursor copy, dinv = rsqrt(cnt+1)
__global__ void k_scan(const int* __restrict__ cnt, int* rowptr, int* cursor,
                       float* dinv, int n) {
    __shared__ int s[1024];
    __shared__ int carry;
    int tid = threadIdx.x;
    if (tid == 0) carry = 0;
    __syncthreads();
    for (int base = 0; base < n; base += 1024) {
        int i = base + tid;
        int v = (i < n) ? cnt[i] : 0;
        s[tid] = v;
        __syncthreads();
        for (int off = 1; off < 1024; off <<= 1) {
            int t = (tid >= off) ? s[tid - off] : 0;
            __syncthreads();
            s[tid] += t;
            __syncthreads();
        }
        int incl = s[tid];
        int excl = incl - v + carry;
        if (i < n) {
            rowptr[i] = excl;
            cursor[i] = excl;
            dinv[i] = rsqrtf((float)v + 1.0f);
        }
        __syncthreads();
        if (tid == 1023) carry += incl;
        __syncthreads();
    }
    if (tid == 0) rowptr[n] = carry;
}

__global__ void k_fill(const void* __restrict__ ei,
                       const float* __restrict__ dinv, int* cursor,
                       int* csr_src, float* csr_w, int E, int N) {
    int is64 = g_idx64;
    int e = blockIdx.x * blockDim.x + threadIdx.x;
    if (e < E) {
        int s = idx_at(ei, e, is64);
        int d = idx_at(ei, (long long)E + e, is64);
        if (s >= 0 && s < N && d >= 0 && d < N) {
            int pos = atomicAdd(&cursor[d], 1);
            csr_src[pos] = s;
            csr_w[pos] = dinv[s] * dinv[d];
        }
    }
}

// starts[g] = first index i with batch[i] >= g   (batch is sorted)
__global__ void k_starts(const void* __restrict__ batch, int n, int* starts) {
    int is64 = g_idx64;
    int g = threadIdx.x;
    if (g < NGRAPHS) {
        int lo = 0, hi = n;
        while (lo < hi) {
            int mid = (lo + hi) >> 1;
            if (idx_at(batch, mid, is64) < g) lo = mid + 1; else hi = mid;
        }
        starts[g] = lo;
    }
}

// ---------------- gather aggregation: block per node, thread per feature ----------------
// agg[i,f] = bias[f] + dinv[i]^2 * h[i,f] + sum_{e in CSR(i)} w_e * h[src_e, f]
__global__ void k_aggregate(const float* __restrict__ h,
                            const int* __restrict__ rowptr,
                            const int* __restrict__ csr_src,
                            const float* __restrict__ csr_w,
                            const float* __restrict__ dinv,
                            const float* __restrict__ bias,
                            float* __restrict__ agg, int F) {
    int i = blockIdx.x;
    int f = threadIdx.x;
    __shared__ int s_src[128];
    __shared__ float s_w[128];
    int e0 = rowptr[i], e1 = rowptr[i + 1];
    float acc = 0.f;
    for (int base = e0; base < e1; base += 128) {
        int cnt = e1 - base;
        if (cnt > 128) cnt = 128;
        __syncthreads();
        for (int t = threadIdx.x; t < cnt; t += blockDim.x) {
            s_src[t] = csr_src[base + t];
            s_w[t]   = csr_w[base + t];
        }
        __syncthreads();
        if (f < F) {
            int t = 0;
            for (; t + 4 <= cnt; t += 4) {
                float v0 = h[(size_t)s_src[t + 0] * F + f] * s_w[t + 0];
                float v1 = h[(size_t)s_src[t + 1] * F + f] * s_w[t + 1];
                float v2 = h[(size_t)s_src[t + 2] * F + f] * s_w[t + 2];
                float v3 = h[(size_t)s_src[t + 3] * F + f] * s_w[t + 3];
                acc += (v0 + v1) + (v2 + v3);
            }
            for (; t < cnt; t++)
                acc += h[(size_t)s_src[t] * F + f] * s_w[t];
        }
    }
    if (f < F) {
        float d = dinv[i];
        agg[(size_t)i * F + f] = bias[f] + acc + d * d * h[(size_t)i * F + f];
    }
}

// ---------------- tiled fp32 GEMM: C[M,N] = op(A[M,K]) @ B[K,N] ----------------
__global__ __launch_bounds__(256) void k_gemm(const float* __restrict__ A,
                                              const float* __restrict__ B,
                                              float* __restrict__ C,
                                              int M, int K, int N, int reluA) {
    __shared__ float As[64][17];
    __shared__ float Bs[16][65];
    int tid = threadIdx.x;
    int tx = tid & 15, ty = tid >> 4;
    int row0 = blockIdx.y * 64, col0 = blockIdx.x * 64;
    float acc[4][4] = {};
    for (int kk = 0; kk < K; kk += 16) {
        #pragma unroll
        for (int r = 0; r < 4; r++) {
            int idx = tid + r * 256;
            int ar = idx >> 4, ac = idx & 15;
            int grow = row0 + ar, gcol = kk + ac;
            float v = (grow < M && gcol < K) ? A[(size_t)grow * K + gcol] : 0.f;
            if (reluA) v = fmaxf(v, 0.f);
            As[ar][ac] = v;
        }
        #pragma unroll
        for (int r = 0; r < 4; r++) {
            int idx = tid + r * 256;
            int br = idx >> 6, bc = idx & 63;
            int grow = kk + br, gcol = col0 + bc;
            Bs[br][bc] = (grow < K && gcol < N) ? B[(size_t)grow * N + gcol] : 0.f;
        }
        __syncthreads();
        #pragma unroll
        for (int k = 0; k < 16; k++) {
            float a[4], b[4];
            #pragma unroll
            for (int i = 0; i < 4; i++) a[i] = As[ty * 4 + i][k];
            #pragma unroll
            for (int j = 0; j < 4; j++) b[j] = Bs[k][tx * 4 + j];
            #pragma unroll
            for (int i = 0; i < 4; i++)
                #pragma unroll
                for (int j = 0; j < 4; j++) acc[i][j] += a[i] * b[j];
        }
        __syncthreads();
    }
    #pragma unroll
    for (int i = 0; i < 4; i++) {
        int row = row0 + ty * 4 + i;
        if (row >= M) continue;
        #pragma unroll
        for (int j = 0; j < 4; j++) {
            int col = col0 + tx * 4 + j;
            if (col < N) C[(size_t)row * N + col] = acc[i][j];
        }
    }
}

// ---------------- final GEMM with dense-batch scatter epilogue ----------------
__global__ __launch_bounds__(256) void k_gemm_final(const float* __restrict__ A,
                                                    const float* __restrict__ B,
                                                    const float* __restrict__ bias,
                                                    const void* __restrict__ batch,
                                                    const int* __restrict__ starts,
                                                    float* __restrict__ out,
                                                    int M, int K, int N, int max_num) {
    __shared__ float As[64][17];
    __shared__ float Bs[16][65];
    int is64 = g_idx64;
    int tid = threadIdx.x;
    int tx = tid & 15, ty = tid >> 4;
    int row0 = blockIdx.y * 64, col0 = blockIdx.x * 64;
    float acc[4][4] = {};
    for (int kk = 0; kk < K; kk += 16) {
        #pragma unroll
        for (int r = 0; r < 4; r++) {
            int idx = tid + r * 256;
            int ar = idx >> 4, ac = idx & 15;
            int grow = row0 + ar, gcol = kk + ac;
            float v = (grow < M && gcol < K) ? fmaxf(A[(size_t)grow * K + gcol], 0.f) : 0.f;
            As[ar][ac] = v;
        }
        #pragma unroll
        for (int r = 0; r < 4; r++) {
            int idx = tid + r * 256;
            int br = idx >> 6, bc = idx & 63;
            int grow = kk + br, gcol = col0 + bc;
            Bs[br][bc] = (grow < K && gcol < N) ? B[(size_t)grow * N + gcol] : 0.f;
        }
        __syncthreads();
        #pragma unroll
        for (int k = 0; k < 16; k++) {
            float a[4], b[4];
            #pragma unroll
            for (int i = 0; i < 4; i++) a[i] = As[ty * 4 + i][k];
            #pragma unroll
            for (int j = 0; j < 4; j++) b[j] = Bs[k][tx * 4 + j];
            #pragma unroll
            for (int i = 0; i < 4; i++)
                #pragma unroll
                for (int j = 0; j < 4; j++) acc[i][j] += a[i] * b[j];
        }
        __syncthreads();
    }
    #pragma unroll
    for (int i = 0; i < 4; i++) {
        int row = row0 + ty * 4 + i;
        if (row >= M) continue;
        int bg = idx_at(batch, row, is64);
        int pos = row - starts[bg];
        if (pos >= max_num) continue;
        float* orow = out + ((size_t)bg * max_num + pos) * N;
        #pragma unroll
        for (int j = 0; j < 4; j++) {
            int col = col0 + tx * 4 + j;
            if (col < N) orow[col] = acc[i][j] + bias[col];
        }
    }
}

// ---------------- host launcher ----------------
extern "C" void kernel_launch(void* const* d_in, const int* in_sizes, int n_in,
                              void* d_out, int out_size) {
    const float* x     = (const float*)d_in[0];
    const void*  ei    = d_in[1];
    const void*  batch = d_in[2];
    const float* W1 = (const float*)d_in[4];
    const float* b1 = (const float*)d_in[5];
    const float* W2 = (const float*)d_in[6];
    const float* b2 = (const float*)d_in[7];
    const float* W3 = (const float*)d_in[8];
    const float* b3 = (const float*)d_in[9];
    const float* Wf = (const float*)d_in[10];
    const float* bf = (const float*)d_in[11];
    float* out = (float*)d_out;

    int N  = in_sizes[2];            // nodes
    int E  = in_sizes[1] / 2;        // edges
    int F0 = in_sizes[0] / N;        // 54
    int F2 = in_sizes[6] / F0;       // 108
    int F3 = in_sizes[8] / F2;       // 216
    int FO = in_sizes[10] / F3;      // 200
    int max_num = out_size / (NGRAPHS * FO);

    float *p_h, *p_agg, *p_dinv, *p_csr_w;
    int *p_cnt, *p_rowptr, *p_cursor, *p_csr_src, *p_starts;
    cudaGetSymbolAddress((void**)&p_h, g_h);
    cudaGetSymbolAddress((void**)&p_agg, g_agg);
    cudaGetSymbolAddress((void**)&p_dinv, g_dinv);
    cudaGetSymbolAddress((void**)&p_cnt, g_cnt);
    cudaGetSymbolAddress((void**)&p_rowptr, g_rowptr);
    cudaGetSymbolAddress((void**)&p_cursor, g_cursor);
    cudaGetSymbolAddress((void**)&p_csr_src, g_csr_src);
    cudaGetSymbolAddress((void**)&p_csr_w, g_csr_w);
    cudaGetSymbolAddress((void**)&p_starts, g_starts);

    const int T = 256;
    int nb_n = (N + T - 1) / T;
    int nb_e = (E + T - 1) / T;

    // index dtype detection (writes g_idx64; later kernels read it)
    k_detect<<<1, 32>>>((const int*)ei);

    // zero dense output (invalid positions stay 0)
    k_zero_f<<<1024, T>>>(out, (size_t)out_size);

    // CSR build + normalization
    k_zero_i<<<nb_n, T>>>(p_cnt, N);
    k_count<<<nb_e, T>>>(ei, p_cnt, E, N);
    k_scan<<<1, 1024>>>(p_cnt, p_rowptr, p_cursor, p_dinv, N);
    k_fill<<<nb_e, T>>>(ei, p_dinv, p_cursor, p_csr_src, p_csr_w, E, N);
    k_starts<<<1, NGRAPHS>>>(batch, N, p_starts);

    // ---- layer 1: F0 -> F0 ----
    {
        dim3 grid((F0 + 63) / 64, (N + 63) / 64);
        k_gemm<<<grid, T>>>(x, W1, p_h, N, F0, F0, 0);
        int bt = ((F0 + 31) / 32) * 32;
        k_aggregate<<<N, bt>>>(p_h, p_rowptr, p_csr_src, p_csr_w, p_dinv, b1, p_agg, F0);
    }
    // ---- layer 2: F0 -> F2 (relu on input) ----
    {
        dim3 grid((F2 + 63) / 64, (N + 63) / 64);
        k_gemm<<<grid, T>>>(p_agg, W2, p_h, N, F0, F2, 1);
        int bt = ((F2 + 31) / 32) * 32;
        k_aggregate<<<N, bt>>>(p_h, p_rowptr, p_csr_src, p_csr_w, p_dinv, b2, p_agg, F2);
    }
    // ---- layer 3: F2 -> F3 (relu on input) ----
    {
        dim3 grid((F3 + 63) / 64, (N + 63) / 64);
        k_gemm<<<grid, T>>>(p_agg, W3, p_h, N, F2, F3, 1);
        int bt = ((F3 + 31) / 32) * 32;
        k_aggregate<<<N, bt>>>(p_h, p_rowptr, p_csr_src, p_csr_w, p_dinv, b3, p_agg, F3);
    }
    // ---- final: relu(agg3) @ Wf + bf -> dense [64, max_num, FO] ----
    {
        dim3 grid((FO + 63) / 64, (N + 63) / 64);
        k_gemm_final<<<grid, T>>>(p_agg, Wf, bf, batch, p_starts, out,
                                  N, F3, FO, max_num);
    }
}

// round 5
// speedup vs baseline: 1.3013x; 1.3013x over previous
#include <cuda_runtime.h>
#include <stdint.h>

#define MAXN 50000
#define MAXE 800000
#define MAXF 216
#define NGRAPHS 64

// ---------------- scratch (static device globals; allocation-free) ----------------
__device__ __align__(16) float g_h[(size_t)MAXN * MAXF];    // layer outputs (post-ReLU)
__device__ __align__(16) float g_agg[(size_t)MAXN * MAXF];  // aggregated features (F_in wide)
__device__ int   g_cnt[MAXN];
__device__ int   g_rowptr[MAXN + 1];
__device__ int   g_cursor[MAXN];
__device__ int   g_csr_src[MAXE];
__device__ float g_csr_w[MAXE];
__device__ float g_dinv[MAXN];
__device__ int   g_starts[NGRAPHS];
__device__ int   g_idx64;   // 1 if index arrays are int64, 0 if int32

// ---------------- index dtype detection ----------------
__global__ void k_detect(const int* __restrict__ w) {
    if (threadIdx.x == 0 && blockIdx.x == 0) {
        int is64 = 1;
        #pragma unroll 1
        for (int i = 1; i < 128; i += 2)
            if (w[i] != 0) { is64 = 0; break; }
        g_idx64 = is64;
    }
}

__device__ __forceinline__ int idx_at(const void* p, long long i, int is64) {
    return is64 ? (int)((const long long*)p)[i] : ((const int*)p)[i];
}

// ---------------- zero kernels ----------------
__global__ void k_zero_f4(float4* p, size_t n4) {
    size_t i = (size_t)blockIdx.x * blockDim.x + threadIdx.x;
    size_t stride = (size_t)gridDim.x * blockDim.x;
    float4 z = {0.f, 0.f, 0.f, 0.f};
    for (; i < n4; i += stride) p[i] = z;
}

__global__ void k_zero_i(int* p, int n) {
    int i = blockIdx.x * blockDim.x + threadIdx.x;
    if (i < n) p[i] = 0;
}

// ---------------- CSR build ----------------
__global__ void k_count(const void* __restrict__ ei, int* cnt, int E, int N) {
    int is64 = g_idx64;
    int i = blockIdx.x * blockDim.x + threadIdx.x;
    if (i < E) {
        int d = idx_at(ei, (long long)E + i, is64);
        if (d >= 0 && d < N) atomicAdd(&cnt[d], 1);
    }
}

// one-pass chunked scan: rowptr (exclusive), cursor copy, dinv = rsqrt(cnt+1)
__global__ void k_scan(const int* __restrict__ cnt, int* rowptr, int* cursor,
                       float* dinv, int n) {
    __shared__ int s[1024];
    int tid = threadIdx.x;
    int chunk = (n + 1023) / 1024;
    int lo = tid * chunk;
    int hi = lo + chunk; if (hi > n) hi = n;
    if (lo > n) lo = n;
    int sum = 0;
    for (int i = lo; i < hi; i++) sum += cnt[i];
    s[tid] = sum;
    __syncthreads();
    for (int off = 1; off < 1024; off <<= 1) {
        int t = (tid >= off) ? s[tid - off] : 0;
        __syncthreads();
        s[tid] += t;
        __syncthreads();
    }
    int run = s[tid] - sum;  // exclusive prefix of this chunk
    for (int i = lo; i < hi; i++) {
        int v = cnt[i];
        rowptr[i] = run;
        cursor[i] = run;
        dinv[i] = rsqrtf((float)v + 1.0f);
        run += v;
    }
    if (tid == 1023) rowptr[n] = run;
}

__global__ void k_fill(const void* __restrict__ ei,
                       const float* __restrict__ dinv, int* cursor,
                       int* csr_src, float* csr_w, int E, int N) {
    int is64 = g_idx64;
    int e = blockIdx.x * blockDim.x + threadIdx.x;
    if (e < E) {
        int s = idx_at(ei, e, is64);
        int d = idx_at(ei, (long long)E + e, is64);
        if (s >= 0 && s < N && d >= 0 && d < N) {
            int pos = atomicAdd(&cursor[d], 1);
            csr_src[pos] = s;
            csr_w[pos] = dinv[s] * dinv[d];
        }
    }
}

// starts[g] = first index i with batch[i] >= g   (batch is sorted)
__global__ void k_starts(const void* __restrict__ batch, int n, int* starts) {
    int is64 = g_idx64;
    int g = threadIdx.x;
    if (g < NGRAPHS) {
        int lo = 0, hi = n;
        while (lo < hi) {
            int mid = (lo + hi) >> 1;
            if (idx_at(batch, mid, is64) < g) lo = mid + 1; else hi = mid;
        }
        starts[g] = lo;
    }
}

// ---------------- gather aggregation: agg = A_hat @ h ----------------
// agg[i,f] = dinv[i]^2 * h[i,f] + sum_{e in CSR(i)} w_e * h[src_e, f]
__global__ void k_aggregate(const float* __restrict__ h,
                            const int* __restrict__ rowptr,
                            const int* __restrict__ csr_src,
                            const float* __restrict__ csr_w,
                            const float* __restrict__ dinv,
                            float* __restrict__ agg, int F) {
    int i = blockIdx.x;
    int f = threadIdx.x;
    __shared__ int s_src[128];
    __shared__ float s_w[128];
    int e0 = rowptr[i], e1 = rowptr[i + 1];
    float acc = 0.f;
    for (int base = e0; base < e1; base += 128) {
        int cnt = e1 - base;
        if (cnt > 128) cnt = 128;
        __syncthreads();
        for (int t = threadIdx.x; t < cnt; t += blockDim.x) {
            s_src[t] = csr_src[base + t];
            s_w[t]   = csr_w[base + t];
        }
        __syncthreads();
        if (f < F) {
            int t = 0;
            for (; t + 4 <= cnt; t += 4) {
                float v0 = h[(size_t)s_src[t + 0] * F + f] * s_w[t + 0];
                float v1 = h[(size_t)s_src[t + 1] * F + f] * s_w[t + 1];
                float v2 = h[(size_t)s_src[t + 2] * F + f] * s_w[t + 2];
                float v3 = h[(size_t)s_src[t + 3] * F + f] * s_w[t + 3];
                acc += (v0 + v1) + (v2 + v3);
            }
            for (; t < cnt; t++)
                acc += h[(size_t)s_src[t] * F + f] * s_w[t];
        }
    }
    if (f < F) {
        float d = dinv[i];
        agg[(size_t)i * F + f] = acc + d * d * h[(size_t)i * F + f];
    }
}

// ---------------- tiled fp32 GEMM: C = A@B + bias (opt relu) ----------------
// 128x64 tile, 256 threads, 8x4 per thread, A staged k-major for LDS.128.
__global__ __launch_bounds__(256) void k_gemm(const float* __restrict__ A,
                                              const float* __restrict__ B,
                                              const float* __restrict__ bias,
                                              float* __restrict__ C,
                                              int M, int K, int N, int relu) {
    __shared__ float As[16][132];
    __shared__ float Bs[16][68];
    int tid = threadIdx.x;
    int tx = tid & 15, ty = tid >> 4;
    int row0 = blockIdx.y * 128, col0 = blockIdx.x * 64;
    float acc[8][4] = {};
    for (int kk = 0; kk < K; kk += 16) {
        {   // A tile: thread handles row tid>>1, k-range (tid&1)*8..+7
            int r = tid >> 1;
            int kbase = (tid & 1) * 8;
            int grow = row0 + r;
            #pragma unroll
            for (int j = 0; j < 8; j++) {
                int gk = kk + kbase + j;
                As[kbase + j][r] = (grow < M && gk < K) ? A[(size_t)grow * K + gk] : 0.f;
            }
        }
        #pragma unroll
        for (int rl = 0; rl < 4; rl++) {  // B tile: 16x64
            int idx = tid + rl * 256;
            int br = idx >> 6, bc = idx & 63;
            int gk = kk + br, gc = col0 + bc;
            Bs[br][bc] = (gk < K && gc < N) ? B[(size_t)gk * N + gc] : 0.f;
        }
        __syncthreads();
        #pragma unroll
        for (int k = 0; k < 16; k++) {
            float a[8], b[4];
            #pragma unroll
            for (int i = 0; i < 8; i++) a[i] = As[k][ty * 8 + i];
            #pragma unroll
            for (int j = 0; j < 4; j++) b[j] = Bs[k][tx * 4 + j];
            #pragma unroll
            for (int i = 0; i < 8; i++)
                #pragma unroll
                for (int j = 0; j < 4; j++) acc[i][j] += a[i] * b[j];
        }
        __syncthreads();
    }
    #pragma unroll
    for (int i = 0; i < 8; i++) {
        int row = row0 + ty * 8 + i;
        if (row >= M) continue;
        #pragma unroll
        for (int j = 0; j < 4; j++) {
            int col = col0 + tx * 4 + j;
            if (col < N) {
                float v = acc[i][j] + bias[col];
                if (relu) v = fmaxf(v, 0.f);
                C[(size_t)row * N + col] = v;
            }
        }
    }
}

// ---------------- final GEMM with dense-batch scatter epilogue ----------------
__global__ __launch_bounds__(256) void k_gemm_final(const float* __restrict__ A,
                                                    const float* __restrict__ B,
                                                    const float* __restrict__ bias,
                                                    const void* __restrict__ batch,
                                                    const int* __restrict__ starts,
                                                    float* __restrict__ out,
                                                    int M, int K, int N, int max_num) {
    __shared__ float As[16][132];
    __shared__ float Bs[16][68];
    int is64 = g_idx64;
    int tid = threadIdx.x;
    int tx = tid & 15, ty = tid >> 4;
    int row0 = blockIdx.y * 128, col0 = blockIdx.x * 64;
    float acc[8][4] = {};
    for (int kk = 0; kk < K; kk += 16) {
        {
            int r = tid >> 1;
            int kbase = (tid & 1) * 8;
            int grow = row0 + r;
            #pragma unroll
            for (int j = 0; j < 8; j++) {
                int gk = kk + kbase + j;
                As[kbase + j][r] = (grow < M && gk < K) ? A[(size_t)grow * K + gk] : 0.f;
            }
        }
        #pragma unroll
        for (int rl = 0; rl < 4; rl++) {
            int idx = tid + rl * 256;
            int br = idx >> 6, bc = idx & 63;
            int gk = kk + br, gc = col0 + bc;
            Bs[br][bc] = (gk < K && gc < N) ? B[(size_t)gk * N + gc] : 0.f;
        }
        __syncthreads();
        #pragma unroll
        for (int k = 0; k < 16; k++) {
            float a[8], b[4];
            #pragma unroll
            for (int i = 0; i < 8; i++) a[i] = As[k][ty * 8 + i];
            #pragma unroll
            for (int j = 0; j < 4; j++) b[j] = Bs[k][tx * 4 + j];
            #pragma unroll
            for (int i = 0; i < 8; i++)
                #pragma unroll
                for (int j = 0; j < 4; j++) acc[i][j] += a[i] * b[j];
        }
        __syncthreads();
    }
    #pragma unroll
    for (int i = 0; i < 8; i++) {
        int row = row0 + ty * 8 + i;
        if (row >= M) continue;
        int bg = idx_at(batch, row, is64);
        int pos = row - starts[bg];
        if (pos >= max_num) continue;
        float* orow = out + ((size_t)bg * max_num + pos) * N;
        #pragma unroll
        for (int j = 0; j < 4; j++) {
            int col = col0 + tx * 4 + j;
            if (col < N) orow[col] = acc[i][j] + bias[col];
        }
    }
}

// ---------------- host launcher ----------------
extern "C" void kernel_launch(void* const* d_in, const int* in_sizes, int n_in,
                              void* d_out, int out_size) {
    const float* x     = (const float*)d_in[0];
    const void*  ei    = d_in[1];
    const void*  batch = d_in[2];
    const float* W1 = (const float*)d_in[4];
    const float* b1 = (const float*)d_in[5];
    const float* W2 = (const float*)d_in[6];
    const float* b2 = (const float*)d_in[7];
    const float* W3 = (const float*)d_in[8];
    const float* b3 = (const float*)d_in[9];
    const float* Wf = (const float*)d_in[10];
    const float* bf = (const float*)d_in[11];
    float* out = (float*)d_out;

    int N  = in_sizes[2];            // nodes
    int E  = in_sizes[1] / 2;        // edges
    int F0 = in_sizes[0] / N;        // 54
    int F2 = in_sizes[6] / F0;       // 108
    int F3 = in_sizes[8] / F2;       // 216
    int FO = in_sizes[10] / F3;      // 200
    int max_num = out_size / (NGRAPHS * FO);

    float *p_h, *p_agg, *p_dinv, *p_csr_w;
    int *p_cnt, *p_rowptr, *p_cursor, *p_csr_src, *p_starts;
    cudaGetSymbolAddress((void**)&p_h, g_h);
    cudaGetSymbolAddress((void**)&p_agg, g_agg);
    cudaGetSymbolAddress((void**)&p_dinv, g_dinv);
    cudaGetSymbolAddress((void**)&p_cnt, g_cnt);
    cudaGetSymbolAddress((void**)&p_rowptr, g_rowptr);
    cudaGetSymbolAddress((void**)&p_cursor, g_cursor);
    cudaGetSymbolAddress((void**)&p_csr_src, g_csr_src);
    cudaGetSymbolAddress((void**)&p_csr_w, g_csr_w);
    cudaGetSymbolAddress((void**)&p_starts, g_starts);

    const int T = 256;
    int nb_n = (N + T - 1) / T;
    int nb_e = (E + T - 1) / T;

    k_detect<<<1, 32>>>((const int*)ei);
    k_zero_f4<<<1024, T>>>((float4*)out, (size_t)out_size / 4);

    // CSR build + normalization
    k_zero_i<<<nb_n, T>>>(p_cnt, N);
    k_count<<<nb_e, T>>>(ei, p_cnt, E, N);
    k_scan<<<1, 1024>>>(p_cnt, p_rowptr, p_cursor, p_dinv, N);
    k_fill<<<nb_e, T>>>(ei, p_dinv, p_cursor, p_csr_src, p_csr_w, E, N);
    k_starts<<<1, NGRAPHS>>>(batch, N, p_starts);

    int mb = (N + 127) / 128;

    // ---- layer 1: agg(x) @ W1 + b1, relu ----
    {
        int bt = ((F0 + 31) / 32) * 32;
        k_aggregate<<<N, bt>>>(x, p_rowptr, p_csr_src, p_csr_w, p_dinv, p_agg, F0);
        dim3 grid((F0 + 63) / 64, mb);
        k_gemm<<<grid, T>>>(p_agg, W1, b1, p_h, N, F0, F0, 1);
    }
    // ---- layer 2: agg(h1) @ W2 + b2, relu ----
    {
        int bt = ((F0 + 31) / 32) * 32;
        k_aggregate<<<N, bt>>>(p_h, p_rowptr, p_csr_src, p_csr_w, p_dinv, p_agg, F0);
        dim3 grid((F2 + 63) / 64, mb);
        k_gemm<<<grid, T>>>(p_agg, W2, b2, p_h, N, F0, F2, 1);
    }
    // ---- layer 3: agg(h2) @ W3 + b3, relu ----
    {
        int bt = ((F2 + 31) / 32) * 32;
        k_aggregate<<<N, bt>>>(p_h, p_rowptr, p_csr_src, p_csr_w, p_dinv, p_agg, F2);
        dim3 grid((F3 + 63) / 64, mb);
        k_gemm<<<grid, T>>>(p_agg, W3, b3, p_h, N, F2, F3, 1);
    }
    // ---- final: h3 @ Wf + bf -> dense [64, max_num, FO] ----
    {
        dim3 grid((FO + 63) / 64, mb);
        k_gemm_final<<<grid, T>>>(p_h, Wf, bf, batch, p_starts, out,
                                  N, F3, FO, max_num);
    }
}

// round 6
// speedup vs baseline: 1.4429x; 1.1088x over previous
#include <cuda_runtime.h>
#include <stdint.h>

#define MAXN 50000
#define MAXE 800000
#define MAXF 216
#define NGRAPHS 64

// ---------------- scratch (static device globals; allocation-free) ----------------
__device__ __align__(16) float g_h[(size_t)MAXN * MAXF];    // layer outputs (post-ReLU)
__device__ __align__(16) float g_agg[(size_t)MAXN * MAXF];  // aggregated features (F_in wide)
__device__ int   g_cnt[MAXN];
__device__ int   g_rowptr[MAXN + 1];
__device__ int   g_cursor[MAXN];
__device__ int   g_csr_src[MAXE];
__device__ float g_csr_w[MAXE];
__device__ float g_dinv[MAXN];
__device__ int   g_starts[NGRAPHS];
__device__ int   g_idx64;   // 1 if index arrays are int64, 0 if int32

// ---------------- index dtype detection ----------------
__global__ void k_detect(const int* __restrict__ w) {
    if (threadIdx.x == 0 && blockIdx.x == 0) {
        int is64 = 1;
        #pragma unroll 1
        for (int i = 1; i < 128; i += 2)
            if (w[i] != 0) { is64 = 0; break; }
        g_idx64 = is64;
    }
}

__device__ __forceinline__ int idx_at(const void* p, long long i, int is64) {
    return is64 ? (int)((const long long*)p)[i] : ((const int*)p)[i];
}

// ---------------- zero kernels ----------------
__global__ void k_zero_f4(float4* p, size_t n4) {
    size_t i = (size_t)blockIdx.x * blockDim.x + threadIdx.x;
    size_t stride = (size_t)gridDim.x * blockDim.x;
    float4 z = {0.f, 0.f, 0.f, 0.f};
    for (; i < n4; i += stride) p[i] = z;
}

__global__ void k_zero_i(int* p, int n) {
    int i = blockIdx.x * blockDim.x + threadIdx.x;
    if (i < n) p[i] = 0;
}

// ---------------- CSR build ----------------
__global__ void k_count(const void* __restrict__ ei, int* cnt, int E, int N) {
    int is64 = g_idx64;
    int i = blockIdx.x * blockDim.x + threadIdx.x;
    if (i < E) {
        int d = idx_at(ei, (long long)E + i, is64);
        if (d >= 0 && d < N) atomicAdd(&cnt[d], 1);
    }
}

// one-pass chunked scan: rowptr (exclusive), cursor copy, dinv = rsqrt(cnt+1)
__global__ void k_scan(const int* __restrict__ cnt, int* rowptr, int* cursor,
                       float* dinv, int n) {
    __shared__ int s[1024];
    int tid = threadIdx.x;
    int chunk = (n + 1023) / 1024;
    int lo = tid * chunk;
    int hi = lo + chunk; if (hi > n) hi = n;
    if (lo > n) lo = n;
    int sum = 0;
    for (int i = lo; i < hi; i++) sum += cnt[i];
    s[tid] = sum;
    __syncthreads();
    for (int off = 1; off < 1024; off <<= 1) {
        int t = (tid >= off) ? s[tid - off] : 0;
        __syncthreads();
        s[tid] += t;
        __syncthreads();
    }
    int run = s[tid] - sum;  // exclusive prefix of this chunk
    for (int i = lo; i < hi; i++) {
        int v = cnt[i];
        rowptr[i] = run;
        cursor[i] = run;
        dinv[i] = rsqrtf((float)v + 1.0f);
        run += v;
    }
    if (tid == 1023) rowptr[n] = run;
}

__global__ void k_fill(const void* __restrict__ ei,
                       const float* __restrict__ dinv, int* cursor,
                       int* csr_src, float* csr_w, int E, int N) {
    int is64 = g_idx64;
    int e = blockIdx.x * blockDim.x + threadIdx.x;
    if (e < E) {
        int s = idx_at(ei, e, is64);
        int d = idx_at(ei, (long long)E + e, is64);
        if (s >= 0 && s < N && d >= 0 && d < N) {
            int pos = atomicAdd(&cursor[d], 1);
            csr_src[pos] = s;
            csr_w[pos] = dinv[s] * dinv[d];
        }
    }
}

// starts[g] = first index i with batch[i] >= g   (batch is sorted)
__global__ void k_starts(const void* __restrict__ batch, int n, int* starts) {
    int is64 = g_idx64;
    int g = threadIdx.x;
    if (g < NGRAPHS) {
        int lo = 0, hi = n;
        while (lo < hi) {
            int mid = (lo + hi) >> 1;
            if (idx_at(batch, mid, is64) < g) lo = mid + 1; else hi = mid;
        }
        starts[g] = lo;
    }
}

// ---------------- gather aggregation: agg = A_hat @ h ----------------
__global__ void k_aggregate(const float* __restrict__ h,
                            const int* __restrict__ rowptr,
                            const int* __restrict__ csr_src,
                            const float* __restrict__ csr_w,
                            const float* __restrict__ dinv,
                            float* __restrict__ agg, int F) {
    int i = blockIdx.x;
    int f = threadIdx.x;
    __shared__ int s_src[128];
    __shared__ float s_w[128];
    int e0 = rowptr[i], e1 = rowptr[i + 1];
    float acc = 0.f;
    for (int base = e0; base < e1; base += 128) {
        int cnt = e1 - base;
        if (cnt > 128) cnt = 128;
        __syncthreads();
        for (int t = threadIdx.x; t < cnt; t += blockDim.x) {
            s_src[t] = csr_src[base + t];
            s_w[t]   = csr_w[base + t];
        }
        __syncthreads();
        if (f < F) {
            int t = 0;
            for (; t + 4 <= cnt; t += 4) {
                float v0 = h[(size_t)s_src[t + 0] * F + f] * s_w[t + 0];
                float v1 = h[(size_t)s_src[t + 1] * F + f] * s_w[t + 1];
                float v2 = h[(size_t)s_src[t + 2] * F + f] * s_w[t + 2];
                float v3 = h[(size_t)s_src[t + 3] * F + f] * s_w[t + 3];
                acc += (v0 + v1) + (v2 + v3);
            }
            for (; t < cnt; t++)
                acc += h[(size_t)s_src[t] * F + f] * s_w[t];
        }
    }
    if (f < F) {
        float d = dinv[i];
        agg[(size_t)i * F + f] = acc + d * d * h[(size_t)i * F + f];
    }
}

// ---------------- tf32 tensor-core GEMM ----------------
// C[M,N] = A[M,K] @ B[K,N] (+bias, opt relu / dense-batch remap)
// BM=128, BN=64, BK=16. 8 warps: wm in {0,1} (64 rows), wn in {0..3} (16 cols).
// Each warp: 4 m-tiles x 2 n-tiles of m16n8k8.

__device__ __forceinline__ float to_tf32(float x) {
    float y;
    asm("cvt.rna.tf32.f32 %0, %1;" : "=f"(y) : "f"(x));
    return y;
}

__device__ __forceinline__ void mma_tf32(float& d0, float& d1, float& d2, float& d3,
                                         float a0, float a1, float a2, float a3,
                                         float b0, float b1) {
    asm("mma.sync.aligned.m16n8k8.row.col.f32.tf32.tf32.f32 "
        "{%0,%1,%2,%3},{%4,%5,%6,%7},{%8,%9},{%0,%1,%2,%3};"
        : "+f"(d0), "+f"(d1), "+f"(d2), "+f"(d3)
        : "r"(__float_as_uint(a0)), "r"(__float_as_uint(a1)),
          "r"(__float_as_uint(a2)), "r"(__float_as_uint(a3)),
          "r"(__float_as_uint(b0)), "r"(__float_as_uint(b1)));
}

// MODE 0: C = relu(A@B + bias), row-major.  MODE 1: dense-batch remap, no relu.
template <int MODE>
__global__ __launch_bounds__(256) void k_gemm_tc(const float* __restrict__ A,
                                                 const float* __restrict__ B,
                                                 const float* __restrict__ bias,
                                                 const void* __restrict__ batch,
                                                 const int* __restrict__ starts,
                                                 float* __restrict__ C,
                                                 int M, int K, int N, int max_num) {
    __shared__ float As[16][132];   // k-major: As[k][m]
    __shared__ float Bs[16][68];    // k-major: Bs[k][n]
    int tid = threadIdx.x;
    int warp = tid >> 5, lane = tid & 31;
    int wm = warp >> 2, wn = warp & 3;
    int gid = lane >> 2, t4 = lane & 3;   // groupID, thread-in-group
    int row0 = blockIdx.y * 128, col0 = blockIdx.x * 64;

    float acc[4][2][4];
    #pragma unroll
    for (int mt = 0; mt < 4; mt++)
        #pragma unroll
        for (int nt = 0; nt < 2; nt++)
            #pragma unroll
            for (int r = 0; r < 4; r++) acc[mt][nt][r] = 0.f;

    for (int kk = 0; kk < K; kk += 16) {
        {   // A tile: thread handles row tid>>1, k-range (tid&1)*8..+7
            int r = tid >> 1;
            int kbase = (tid & 1) * 8;
            int grow = row0 + r;
            #pragma unroll
            for (int j = 0; j < 8; j++) {
                int gk = kk + kbase + j;
                float v = (grow < M && gk < K) ? A[(size_t)grow * K + gk] : 0.f;
                As[kbase + j][r] = to_tf32(v);
            }
        }
        #pragma unroll
        for (int rl = 0; rl < 4; rl++) {  // B tile: 16x64
            int idx = tid + rl * 256;
            int br = idx >> 6, bc = idx & 63;
            int gk = kk + br, gc = col0 + bc;
            float v = (gk < K && gc < N) ? B[(size_t)gk * N + gc] : 0.f;
            Bs[br][bc] = to_tf32(v);
        }
        __syncthreads();
        #pragma unroll
        for (int k8 = 0; k8 < 16; k8 += 8) {
            float bf[2][2];
            #pragma unroll
            for (int nt = 0; nt < 2; nt++) {
                int bc = wn * 16 + nt * 8 + gid;
                bf[nt][0] = Bs[k8 + t4][bc];
                bf[nt][1] = Bs[k8 + t4 + 4][bc];
            }
            #pragma unroll
            for (int mt = 0; mt < 4; mt++) {
                int ar = wm * 64 + mt * 16 + gid;
                float a0 = As[k8 + t4][ar];
                float a1 = As[k8 + t4][ar + 8];
                float a2 = As[k8 + t4 + 4][ar];
                float a3 = As[k8 + t4 + 4][ar + 8];
                #pragma unroll
                for (int nt = 0; nt < 2; nt++)
                    mma_tf32(acc[mt][nt][0], acc[mt][nt][1], acc[mt][nt][2], acc[mt][nt][3],
                             a0, a1, a2, a3, bf[nt][0], bf[nt][1]);
            }
        }
        __syncthreads();
    }

    int is64 = (MODE == 1) ? g_idx64 : 0;
    #pragma unroll
    for (int mt = 0; mt < 4; mt++) {
        #pragma unroll
        for (int half = 0; half < 2; half++) {
            int row = row0 + wm * 64 + mt * 16 + gid + half * 8;
            if (row >= M) continue;
            float* orow;
            if (MODE == 0) {
                orow = C + (size_t)row * N;
            } else {
                int bg = idx_at(batch, row, is64);
                int pos = row - starts[bg];
                if (pos >= max_num) continue;
                orow = C + ((size_t)bg * max_num + pos) * N;
            }
            #pragma unroll
            for (int nt = 0; nt < 2; nt++) {
                int col = col0 + wn * 16 + nt * 8 + t4 * 2;
                #pragma unroll
                for (int c = 0; c < 2; c++) {
                    if (col + c < N) {
                        float v = acc[mt][nt][half * 2 + c] + bias[col + c];
                        if (MODE == 0) v = fmaxf(v, 0.f);
                        orow[col + c] = v;
                    }
                }
            }
        }
    }
}

// ---------------- host launcher ----------------
extern "C" void kernel_launch(void* const* d_in, const int* in_sizes, int n_in,
                              void* d_out, int out_size) {
    const float* x     = (const float*)d_in[0];
    const void*  ei    = d_in[1];
    const void*  batch = d_in[2];
    const float* W1 = (const float*)d_in[4];
    const float* b1 = (const float*)d_in[5];
    const float* W2 = (const float*)d_in[6];
    const float* b2 = (const float*)d_in[7];
    const float* W3 = (const float*)d_in[8];
    const float* b3 = (const float*)d_in[9];
    const float* Wf = (const float*)d_in[10];
    const float* bf = (const float*)d_in[11];
    float* out = (float*)d_out;

    int N  = in_sizes[2];            // nodes
    int E  = in_sizes[1] / 2;        // edges
    int F0 = in_sizes[0] / N;        // 54
    int F2 = in_sizes[6] / F0;       // 108
    int F3 = in_sizes[8] / F2;       // 216
    int FO = in_sizes[10] / F3;      // 200
    int max_num = out_size / (NGRAPHS * FO);

    float *p_h, *p_agg, *p_dinv, *p_csr_w;
    int *p_cnt, *p_rowptr, *p_cursor, *p_csr_src, *p_starts;
    cudaGetSymbolAddress((void**)&p_h, g_h);
    cudaGetSymbolAddress((void**)&p_agg, g_agg);
    cudaGetSymbolAddress((void**)&p_dinv, g_dinv);
    cudaGetSymbolAddress((void**)&p_cnt, g_cnt);
    cudaGetSymbolAddress((void**)&p_rowptr, g_rowptr);
    cudaGetSymbolAddress((void**)&p_cursor, g_cursor);
    cudaGetSymbolAddress((void**)&p_csr_src, g_csr_src);
    cudaGetSymbolAddress((void**)&p_csr_w, g_csr_w);
    cudaGetSymbolAddress((void**)&p_starts, g_starts);

    const int T = 256;
    int nb_n = (N + T - 1) / T;
    int nb_e = (E + T - 1) / T;

    k_detect<<<1, 32>>>((const int*)ei);
    k_zero_f4<<<1024, T>>>((float4*)out, (size_t)out_size / 4);

    // CSR build + normalization
    k_zero_i<<<nb_n, T>>>(p_cnt, N);
    k_count<<<nb_e, T>>>(ei, p_cnt, E, N);
    k_scan<<<1, 1024>>>(p_cnt, p_rowptr, p_cursor, p_dinv, N);
    k_fill<<<nb_e, T>>>(ei, p_dinv, p_cursor, p_csr_src, p_csr_w, E, N);
    k_starts<<<1, NGRAPHS>>>(batch, N, p_starts);

    int mb = (N + 127) / 128;

    // ---- layer 1: agg(x) @ W1 + b1, relu ----
    {
        int bt = ((F0 + 31) / 32) * 32;
        k_aggregate<<<N, bt>>>(x, p_rowptr, p_csr_src, p_csr_w, p_dinv, p_agg, F0);
        dim3 grid((F0 + 63) / 64, mb);
        k_gemm_tc<0><<<grid, T>>>(p_agg, W1, b1, nullptr, nullptr, p_h, N, F0, F0, 0);
    }
    // ---- layer 2: agg(h1) @ W2 + b2, relu ----
    {
        int bt = ((F0 + 31) / 32) * 32;
        k_aggregate<<<N, bt>>>(p_h, p_rowptr, p_csr_src, p_csr_w, p_dinv, p_agg, F0);
        dim3 grid((F2 + 63) / 64, mb);
        k_gemm_tc<0><<<grid, T>>>(p_agg, W2, b2, nullptr, nullptr, p_h, N, F0, F2, 0);
    }
    // ---- layer 3: agg(h2) @ W3 + b3, relu ----
    {
        int bt = ((F2 + 31) / 32) * 32;
        k_aggregate<<<N, bt>>>(p_h, p_rowptr, p_csr_src, p_csr_w, p_dinv, p_agg, F2);
        dim3 grid((F3 + 63) / 64, mb);
        k_gemm_tc<0><<<grid, T>>>(p_agg, W3, b3, nullptr, nullptr, p_h, N, F2, F3, 0);
    }
    // ---- final: h3 @ Wf + bf -> dense [64, max_num, FO] ----
    {
        dim3 grid((FO + 63) / 64, mb);
        k_gemm_tc<1><<<grid, T>>>(p_h, Wf, bf, batch, p_starts, out,
                                  N, F3, FO, max_num);
    }
}

// round 7
// speedup vs baseline: 1.5738x; 1.0907x over previous
#include <cuda_runtime.h>
#include <stdint.h>

#define MAXN 50000
#define MAXE 800000
#define MAXF 216
#define NGRAPHS 64

// ---------------- scratch (static device globals; allocation-free) ----------------
__device__ __align__(16) float g_h[(size_t)MAXN * MAXF];    // layer outputs (post-ReLU)
__device__ __align__(16) float g_agg[(size_t)MAXN * MAXF];  // aggregated features (F_in wide)
__device__ int   g_cnt[MAXN];
__device__ int   g_rowptr[MAXN + 1];
__device__ int   g_cursor[MAXN];
__device__ int   g_csr_src[MAXE];
__device__ float g_csr_w[MAXE];
__device__ float g_dinv[MAXN];
__device__ int   g_starts[NGRAPHS];
__device__ int   g_idx64;   // 1 if index arrays are int64, 0 if int32

// ---------------- index dtype detection ----------------
__global__ void k_detect(const int* __restrict__ w) {
    if (threadIdx.x == 0 && blockIdx.x == 0) {
        int is64 = 1;
        #pragma unroll 1
        for (int i = 1; i < 128; i += 2)
            if (w[i] != 0) { is64 = 0; break; }
        g_idx64 = is64;
    }
}

__device__ __forceinline__ int idx_at(const void* p, long long i, int is64) {
    return is64 ? (int)((const long long*)p)[i] : ((const int*)p)[i];
}

// ---------------- zero kernels ----------------
__global__ void k_zero_f4(float4* p, size_t n4) {
    size_t i = (size_t)blockIdx.x * blockDim.x + threadIdx.x;
    size_t stride = (size_t)gridDim.x * blockDim.x;
    float4 z = {0.f, 0.f, 0.f, 0.f};
    for (; i < n4; i += stride) p[i] = z;
}

__global__ void k_zero_i(int* p, int n) {
    int i = blockIdx.x * blockDim.x + threadIdx.x;
    if (i < n) p[i] = 0;
}

// ---------------- CSR build ----------------
__global__ void k_count(const void* __restrict__ ei, int* cnt, int E, int N) {
    int is64 = g_idx64;
    int i = blockIdx.x * blockDim.x + threadIdx.x;
    if (i < E) {
        int d = idx_at(ei, (long long)E + i, is64);
        if (d >= 0 && d < N) atomicAdd(&cnt[d], 1);
    }
}

// one-pass chunked scan: rowptr (exclusive), cursor copy, dinv = rsqrt(cnt+1)
__global__ void k_scan(const int* __restrict__ cnt, int* rowptr, int* cursor,
                       float* dinv, int n) {
    __shared__ int s[1024];
    int tid = threadIdx.x;
    int chunk = (n + 1023) / 1024;
    int lo = tid * chunk;
    int hi = lo + chunk; if (hi > n) hi = n;
    if (lo > n) lo = n;
    int sum = 0;
    for (int i = lo; i < hi; i++) sum += cnt[i];
    s[tid] = sum;
    __syncthreads();
    for (int off = 1; off < 1024; off <<= 1) {
        int t = (tid >= off) ? s[tid - off] : 0;
        __syncthreads();
        s[tid] += t;
        __syncthreads();
    }
    int run = s[tid] - sum;  // exclusive prefix of this chunk
    for (int i = lo; i < hi; i++) {
        int v = cnt[i];
        rowptr[i] = run;
        cursor[i] = run;
        dinv[i] = rsqrtf((float)v + 1.0f);
        run += v;
    }
    if (tid == 1023) rowptr[n] = run;
}

__global__ void k_fill(const void* __restrict__ ei,
                       const float* __restrict__ dinv, int* cursor,
                       int* csr_src, float* csr_w, int E, int N) {
    int is64 = g_idx64;
    int e = blockIdx.x * blockDim.x + threadIdx.x;
    if (e < E) {
        int s = idx_at(ei, e, is64);
        int d = idx_at(ei, (long long)E + e, is64);
        if (s >= 0 && s < N && d >= 0 && d < N) {
            int pos = atomicAdd(&cursor[d], 1);
            csr_src[pos] = s;
            csr_w[pos] = dinv[s] * dinv[d];
        }
    }
}

// starts[g] = first index i with batch[i] >= g   (batch is sorted)
__global__ void k_starts(const void* __restrict__ batch, int n, int* starts) {
    int is64 = g_idx64;
    int g = threadIdx.x;
    if (g < NGRAPHS) {
        int lo = 0, hi = n;
        while (lo < hi) {
            int mid = (lo + hi) >> 1;
            if (idx_at(batch, mid, is64) < g) lo = mid + 1; else hi = mid;
        }
        starts[g] = lo;
    }
}

// ---------------- aggregation: group-per-node, float2 lanes ----------------
// LANES = F/2 float2 columns. GS = group size (32 or 64 threads).
// agg[i,:] = dinv[i]^2 * h[i,:] + sum_{e in CSR(i)} w_e * h[src_e,:]
template <int LANES, int GS>
__global__ __launch_bounds__(256) void k_agg_w(const float2* __restrict__ h2,
                                               const int* __restrict__ rowptr,
                                               const int* __restrict__ csr_src,
                                               const float* __restrict__ csr_w,
                                               const float* __restrict__ dinv,
                                               float2* __restrict__ agg2, int Nn) {
    int gid = threadIdx.x / GS;
    int lane = threadIdx.x % GS;
    int node = blockIdx.x * (256 / GS) + gid;
    if (node >= Nn) return;
    int e0 = rowptr[node], e1 = rowptr[node + 1];
    float ax = 0.f, ay = 0.f;
    bool act = lane < LANES;
    int t = e0;
    for (; t + 4 <= e1; t += 4) {
        int s0 = csr_src[t], s1 = csr_src[t + 1], s2 = csr_src[t + 2], s3 = csr_src[t + 3];
        float w0 = csr_w[t], w1 = csr_w[t + 1], w2 = csr_w[t + 2], w3 = csr_w[t + 3];
        float2 v0, v1, v2, v3;
        if (act) {
            v0 = h2[(size_t)s0 * LANES + lane];
            v1 = h2[(size_t)s1 * LANES + lane];
            v2 = h2[(size_t)s2 * LANES + lane];
            v3 = h2[(size_t)s3 * LANES + lane];
            ax += w0 * v0.x + w1 * v1.x;
            ay += w0 * v0.y + w1 * v1.y;
            ax += w2 * v2.x + w3 * v3.x;
            ay += w2 * v2.y + w3 * v3.y;
        }
    }
    for (; t < e1; t++) {
        int s = csr_src[t];
        float w = csr_w[t];
        if (act) {
            float2 v = h2[(size_t)s * LANES + lane];
            ax += w * v.x;
            ay += w * v.y;
        }
    }
    if (act) {
        float d = dinv[node];
        float2 self = h2[(size_t)node * LANES + lane];
        float2 r;
        r.x = ax + d * d * self.x;
        r.y = ay + d * d * self.y;
        agg2[(size_t)node * LANES + lane] = r;
    }
}

// generic fallback (any F)
__global__ void k_aggregate(const float* __restrict__ h,
                            const int* __restrict__ rowptr,
                            const int* __restrict__ csr_src,
                            const float* __restrict__ csr_w,
                            const float* __restrict__ dinv,
                            float* __restrict__ agg, int F) {
    int i = blockIdx.x;
    int f = threadIdx.x;
    int e0 = rowptr[i], e1 = rowptr[i + 1];
    float acc = 0.f;
    if (f < F) {
        for (int t = e0; t < e1; t++)
            acc += h[(size_t)csr_src[t] * F + f] * csr_w[t];
        float d = dinv[i];
        agg[(size_t)i * F + f] = acc + d * d * h[(size_t)i * F + f];
    }
}

// ---------------- tf32 tensor-core GEMM ----------------
__device__ __forceinline__ float to_tf32(float x) {
    float y;
    asm("cvt.rna.tf32.f32 %0, %1;" : "=f"(y) : "f"(x));
    return y;
}

__device__ __forceinline__ void mma_tf32(float& d0, float& d1, float& d2, float& d3,
                                         float a0, float a1, float a2, float a3,
                                         float b0, float b1) {
    asm("mma.sync.aligned.m16n8k8.row.col.f32.tf32.tf32.f32 "
        "{%0,%1,%2,%3},{%4,%5,%6,%7},{%8,%9},{%0,%1,%2,%3};"
        : "+f"(d0), "+f"(d1), "+f"(d2), "+f"(d3)
        : "r"(__float_as_uint(a0)), "r"(__float_as_uint(a1)),
          "r"(__float_as_uint(a2)), "r"(__float_as_uint(a3)),
          "r"(__float_as_uint(b0)), "r"(__float_as_uint(b1)));
}

// MODE 0: C = relu(A@B + bias), row-major.  MODE 1: dense-batch remap, no relu.
template <int MODE>
__global__ __launch_bounds__(256) void k_gemm_tc(const float* __restrict__ A,
                                                 const float* __restrict__ B,
                                                 const float* __restrict__ bias,
                                                 const void* __restrict__ batch,
                                                 const int* __restrict__ starts,
                                                 float* __restrict__ C,
                                                 int M, int K, int N, int max_num) {
    __shared__ float As[16][132];   // k-major: As[k][m]
    __shared__ float Bs[16][68];    // k-major: Bs[k][n]
    int tid = threadIdx.x;
    int warp = tid >> 5, lane = tid & 31;
    int wm = warp >> 2, wn = warp & 3;
    int gid = lane >> 2, t4 = lane & 3;
    int row0 = blockIdx.y * 128, col0 = blockIdx.x * 64;

    float acc[4][2][4];
    #pragma unroll
    for (int mt = 0; mt < 4; mt++)
        #pragma unroll
        for (int nt = 0; nt < 2; nt++)
            #pragma unroll
            for (int r = 0; r < 4; r++) acc[mt][nt][r] = 0.f;

    for (int kk = 0; kk < K; kk += 16) {
        {
            int r = tid >> 1;
            int kbase = (tid & 1) * 8;
            int grow = row0 + r;
            #pragma unroll
            for (int j = 0; j < 8; j++) {
                int gk = kk + kbase + j;
                float v = (grow < M && gk < K) ? A[(size_t)grow * K + gk] : 0.f;
                As[kbase + j][r] = to_tf32(v);
            }
        }
        #pragma unroll
        for (int rl = 0; rl < 4; rl++) {
            int idx = tid + rl * 256;
            int br = idx >> 6, bc = idx & 63;
            int gk = kk + br, gc = col0 + bc;
            float v = (gk < K && gc < N) ? B[(size_t)gk * N + gc] : 0.f;
            Bs[br][bc] = to_tf32(v);
        }
        __syncthreads();
        #pragma unroll
        for (int k8 = 0; k8 < 16; k8 += 8) {
            float bf[2][2];
            #pragma unroll
            for (int nt = 0; nt < 2; nt++) {
                int bc = wn * 16 + nt * 8 + gid;
                bf[nt][0] = Bs[k8 + t4][bc];
                bf[nt][1] = Bs[k8 + t4 + 4][bc];
            }
            #pragma unroll
            for (int mt = 0; mt < 4; mt++) {
                int ar = wm * 64 + mt * 16 + gid;
                float a0 = As[k8 + t4][ar];
                float a1 = As[k8 + t4][ar + 8];
                float a2 = As[k8 + t4 + 4][ar];
                float a3 = As[k8 + t4 + 4][ar + 8];
                #pragma unroll
                for (int nt = 0; nt < 2; nt++)
                    mma_tf32(acc[mt][nt][0], acc[mt][nt][1], acc[mt][nt][2], acc[mt][nt][3],
                             a0, a1, a2, a3, bf[nt][0], bf[nt][1]);
            }
        }
        __syncthreads();
    }

    int is64 = (MODE == 1) ? g_idx64 : 0;
    #pragma unroll
    for (int mt = 0; mt < 4; mt++) {
        #pragma unroll
        for (int half = 0; half < 2; half++) {
            int row = row0 + wm * 64 + mt * 16 + gid + half * 8;
            if (row >= M) continue;
            float* orow;
            if (MODE == 0) {
                orow = C + (size_t)row * N;
            } else {
                int bg = idx_at(batch, row, is64);
                int pos = row - starts[bg];
                if (pos >= max_num) continue;
                orow = C + ((size_t)bg * max_num + pos) * N;
            }
            #pragma unroll
            for (int nt = 0; nt < 2; nt++) {
                int col = col0 + wn * 16 + nt * 8 + t4 * 2;
                #pragma unroll
                for (int c = 0; c < 2; c++) {
                    if (col + c < N) {
                        float v = acc[mt][nt][half * 2 + c] + bias[col + c];
                        if (MODE == 0) v = fmaxf(v, 0.f);
                        orow[col + c] = v;
                    }
                }
            }
        }
    }
}

// ---------------- aggregation dispatch helper ----------------
static void launch_agg(const float* h, const int* rowptr, const int* csr_src,
                       const float* csr_w, const float* dinv, float* agg,
                       int Nn, int F) {
    if (F == 54) {
        int gpb = 256 / 32;  // groups per block
        k_agg_w<27, 32><<<(Nn + gpb - 1) / gpb, 256>>>(
            (const float2*)h, rowptr, csr_src, csr_w, dinv, (float2*)agg, Nn);
    } else if (F == 108) {
        int gpb = 256 / 64;
        k_agg_w<54, 64><<<(Nn + gpb - 1) / gpb, 256>>>(
            (const float2*)h, rowptr, csr_src, csr_w, dinv, (float2*)agg, Nn);
    } else {
        int bt = ((F + 31) / 32) * 32;
        k_aggregate<<<Nn, bt>>>(h, rowptr, csr_src, csr_w, dinv, agg, F);
    }
}

// ---------------- host launcher ----------------
extern "C" void kernel_launch(void* const* d_in, const int* in_sizes, int n_in,
                              void* d_out, int out_size) {
    const float* x     = (const float*)d_in[0];
    const void*  ei    = d_in[1];
    const void*  batch = d_in[2];
    const float* W1 = (const float*)d_in[4];
    const float* b1 = (const float*)d_in[5];
    const float* W2 = (const float*)d_in[6];
    const float* b2 = (const float*)d_in[7];
    const float* W3 = (const float*)d_in[8];
    const float* b3 = (const float*)d_in[9];
    const float* Wf = (const float*)d_in[10];
    const float* bf = (const float*)d_in[11];
    float* out = (float*)d_out;

    int N  = in_sizes[2];            // nodes
    int E  = in_sizes[1] / 2;        // edges
    int F0 = in_sizes[0] / N;        // 54
    int F2 = in_sizes[6] / F0;       // 108
    int F3 = in_sizes[8] / F2;       // 216
    int FO = in_sizes[10] / F3;      // 200
    int max_num = out_size / (NGRAPHS * FO);

    float *p_h, *p_agg, *p_dinv, *p_csr_w;
    int *p_cnt, *p_rowptr, *p_cursor, *p_csr_src, *p_starts;
    cudaGetSymbolAddress((void**)&p_h, g_h);
    cudaGetSymbolAddress((void**)&p_agg, g_agg);
    cudaGetSymbolAddress((void**)&p_dinv, g_dinv);
    cudaGetSymbolAddress((void**)&p_cnt, g_cnt);
    cudaGetSymbolAddress((void**)&p_rowptr, g_rowptr);
    cudaGetSymbolAddress((void**)&p_cursor, g_cursor);
    cudaGetSymbolAddress((void**)&p_csr_src, g_csr_src);
    cudaGetSymbolAddress((void**)&p_csr_w, g_csr_w);
    cudaGetSymbolAddress((void**)&p_starts, g_starts);

    const int T = 256;
    int nb_n = (N + T - 1) / T;
    int nb_e = (E + T - 1) / T;

    k_detect<<<1, 32>>>((const int*)ei);
    k_zero_f4<<<1024, T>>>((float4*)out, (size_t)out_size / 4);

    // CSR build + normalization
    k_zero_i<<<nb_n, T>>>(p_cnt, N);
    k_count<<<nb_e, T>>>(ei, p_cnt, E, N);
    k_scan<<<1, 1024>>>(p_cnt, p_rowptr, p_cursor, p_dinv, N);
    k_fill<<<nb_e, T>>>(ei, p_dinv, p_cursor, p_csr_src, p_csr_w, E, N);
    k_starts<<<1, NGRAPHS>>>(batch, N, p_starts);

    int mb = (N + 127) / 128;

    // ---- layer 1: agg(x) @ W1 + b1, relu ----
    launch_agg(x, p_rowptr, p_csr_src, p_csr_w, p_dinv, p_agg, N, F0);
    {
        dim3 grid((F0 + 63) / 64, mb);
        k_gemm_tc<0><<<grid, T>>>(p_agg, W1, b1, nullptr, nullptr, p_h, N, F0, F0, 0);
    }
    // ---- layer 2: agg(h1) @ W2 + b2, relu ----
    launch_agg(p_h, p_rowptr, p_csr_src, p_csr_w, p_dinv, p_agg, N, F0);
    {
        dim3 grid((F2 + 63) / 64, mb);
        k_gemm_tc<0><<<grid, T>>>(p_agg, W2, b2, nullptr, nullptr, p_h, N, F0, F2, 0);
    }
    // ---- layer 3: agg(h2) @ W3 + b3, relu ----
    launch_agg(p_h, p_rowptr, p_csr_src, p_csr_w, p_dinv, p_agg, N, F2);
    {
        dim3 grid((F3 + 63) / 64, mb);
        k_gemm_tc<0><<<grid, T>>>(p_agg, W3, b3, nullptr, nullptr, p_h, N, F2, F3, 0);
    }
    // ---- final: h3 @ Wf + bf -> dense [64, max_num, FO] ----
    {
        dim3 grid((FO + 63) / 64, mb);
        k_gemm_tc<1><<<grid, T>>>(p_h, Wf, bf, batch, p_starts, out,
                                  N, F3, FO, max_num);
    }
}

// round 8
// speedup vs baseline: 1.6131x; 1.0250x over previous
#include <cuda_runtime.h>
#include <stdint.h>

#define MAXN 50000
#define MAXE 800000
#define MAXF 216
#define NGRAPHS 64

// ---------------- scratch (static device globals; allocation-free) ----------------
__device__ __align__(16) float g_h[(size_t)MAXN * MAXF];    // layer outputs (post-ReLU)
__device__ __align__(16) float g_agg[(size_t)MAXN * MAXF];  // aggregated features (F_in wide)
__device__ int   g_cnt[MAXN];
__device__ int   g_rowptr[MAXN + 1];
__device__ int   g_cursor[MAXN];
__device__ int   g_csr_src[MAXE];
__device__ float g_csr_w[MAXE];
__device__ float g_dinv[MAXN];
__device__ int   g_starts[NGRAPHS + 1];
__device__ int   g_idx64;   // 1 if index arrays are int64, 0 if int32

// ---------------- index dtype detection ----------------
__global__ void k_detect(const int* __restrict__ w) {
    if (threadIdx.x == 0 && blockIdx.x == 0) {
        int is64 = 1;
        #pragma unroll 1
        for (int i = 1; i < 128; i += 2)
            if (w[i] != 0) { is64 = 0; break; }
        g_idx64 = is64;
    }
}

__device__ __forceinline__ int idx_at(const void* p, long long i, int is64) {
    return is64 ? (int)((const long long*)p)[i] : ((const int*)p)[i];
}

// ---------------- zero kernels ----------------
__global__ void k_zero_i(int* p, int n) {
    int i = blockIdx.x * blockDim.x + threadIdx.x;
    if (i < n) p[i] = 0;
}

// zero only invalid tail rows of the dense output: per graph g,
// rows [valid_g, max_num) of width FO floats (contiguous span).
__global__ void k_zero_tail(float4* __restrict__ out4, const int* __restrict__ starts,
                            int max_num, int FO, int Ntot) {
    int g = blockIdx.y;
    int s0 = starts[g];
    int s1 = (g == NGRAPHS - 1) ? Ntot : starts[g + 1];
    int valid = s1 - s0; if (valid > max_num) valid = max_num;
    size_t rowq = (size_t)FO / 4;                       // float4 per row
    size_t base = ((size_t)g * max_num + valid) * rowq; // first invalid float4
    size_t end  = ((size_t)(g + 1) * max_num) * rowq;
    float4 z = {0.f, 0.f, 0.f, 0.f};
    size_t i = base + blockIdx.x * blockDim.x + threadIdx.x;
    size_t stride = (size_t)gridDim.x * blockDim.x;
    for (; i < end; i += stride) out4[i] = z;
}

// ---------------- CSR build ----------------
__global__ void k_count(const void* __restrict__ ei, int* cnt, int E, int N) {
    int is64 = g_idx64;
    int i = blockIdx.x * blockDim.x + threadIdx.x;
    if (i < E) {
        int d = idx_at(ei, (long long)E + i, is64);
        if (d >= 0 && d < N) atomicAdd(&cnt[d], 1);
    }
}

// one-pass chunked scan: rowptr (exclusive), cursor copy, dinv = rsqrt(cnt+1)
__global__ void k_scan(const int* __restrict__ cnt, int* rowptr, int* cursor,
                       float* dinv, int n) {
    __shared__ int s[1024];
    int tid = threadIdx.x;
    int chunk = (n + 1023) / 1024;
    int lo = tid * chunk;
    int hi = lo + chunk; if (hi > n) hi = n;
    if (lo > n) lo = n;
    int sum = 0;
    for (int i = lo; i < hi; i++) sum += cnt[i];
    s[tid] = sum;
    __syncthreads();
    for (int off = 1; off < 1024; off <<= 1) {
        int t = (tid >= off) ? s[tid - off] : 0;
        __syncthreads();
        s[tid] += t;
        __syncthreads();
    }
    int run = s[tid] - sum;  // exclusive prefix of this chunk
    for (int i = lo; i < hi; i++) {
        int v = cnt[i];
        rowptr[i] = run;
        cursor[i] = run;
        dinv[i] = rsqrtf((float)v + 1.0f);
        run += v;
    }
    if (tid == 1023) rowptr[n] = run;
}

__global__ void k_fill(const void* __restrict__ ei,
                       const float* __restrict__ dinv, int* cursor,
                       int* csr_src, float* csr_w, int E, int N) {
    int is64 = g_idx64;
    int e = blockIdx.x * blockDim.x + threadIdx.x;
    if (e < E) {
        int s = idx_at(ei, e, is64);
        int d = idx_at(ei, (long long)E + e, is64);
        if (s >= 0 && s < N && d >= 0 && d < N) {
            int pos = atomicAdd(&cursor[d], 1);
            csr_src[pos] = s;
            csr_w[pos] = dinv[s] * dinv[d];
        }
    }
}

// starts[g] = first index i with batch[i] >= g   (batch is sorted)
__global__ void k_starts(const void* __restrict__ batch, int n, int* starts) {
    int is64 = g_idx64;
    int g = threadIdx.x;
    if (g < NGRAPHS) {
        int lo = 0, hi = n;
        while (lo < hi) {
            int mid = (lo + hi) >> 1;
            if (idx_at(batch, mid, is64) < g) lo = mid + 1; else hi = mid;
        }
        starts[g] = lo;
    }
}

// ---------------- aggregation: group-per-node, float2 lanes, unroll 8 ----------------
template <int LANES, int GS>
__global__ __launch_bounds__(256) void k_agg_w(const float2* __restrict__ h2,
                                               const int* __restrict__ rowptr,
                                               const int* __restrict__ csr_src,
                                               const float* __restrict__ csr_w,
                                               const float* __restrict__ dinv,
                                               float2* __restrict__ agg2, int Nn) {
    int gid = threadIdx.x / GS;
    int lane = threadIdx.x % GS;
    int node = blockIdx.x * (256 / GS) + gid;
    if (node >= Nn) return;
    int e0 = rowptr[node], e1 = rowptr[node + 1];
    float ax = 0.f, ay = 0.f;
    bool act = lane < LANES;
    int t = e0;
    for (; t + 8 <= e1; t += 8) {
        int   si[8];
        float wi[8];
        #pragma unroll
        for (int u = 0; u < 8; u++) { si[u] = csr_src[t + u]; wi[u] = csr_w[t + u]; }
        if (act) {
            float2 v[8];
            #pragma unroll
            for (int u = 0; u < 8; u++) v[u] = h2[(size_t)si[u] * LANES + lane];
            #pragma unroll
            for (int u = 0; u < 8; u++) { ax += wi[u] * v[u].x; ay += wi[u] * v[u].y; }
        }
    }
    for (; t + 4 <= e1; t += 4) {
        int s0 = csr_src[t], s1 = csr_src[t + 1], s2 = csr_src[t + 2], s3 = csr_src[t + 3];
        float w0 = csr_w[t], w1 = csr_w[t + 1], w2 = csr_w[t + 2], w3 = csr_w[t + 3];
        if (act) {
            float2 v0 = h2[(size_t)s0 * LANES + lane];
            float2 v1 = h2[(size_t)s1 * LANES + lane];
            float2 v2 = h2[(size_t)s2 * LANES + lane];
            float2 v3 = h2[(size_t)s3 * LANES + lane];
            ax += w0 * v0.x + w1 * v1.x + w2 * v2.x + w3 * v3.x;
            ay += w0 * v0.y + w1 * v1.y + w2 * v2.y + w3 * v3.y;
        }
    }
    for (; t < e1; t++) {
        int s = csr_src[t];
        float w = csr_w[t];
        if (act) {
            float2 v = h2[(size_t)s * LANES + lane];
            ax += w * v.x;
            ay += w * v.y;
        }
    }
    if (act) {
        float d = dinv[node];
        float2 self = h2[(size_t)node * LANES + lane];
        float2 r;
        r.x = ax + d * d * self.x;
        r.y = ay + d * d * self.y;
        agg2[(size_t)node * LANES + lane] = r;
    }
}

// generic fallback (any F)
__global__ void k_aggregate(const float* __restrict__ h,
                            const int* __restrict__ rowptr,
                            const int* __restrict__ csr_src,
                            const float* __restrict__ csr_w,
                            const float* __restrict__ dinv,
                            float* __restrict__ agg, int F) {
    int i = blockIdx.x;
    int f = threadIdx.x;
    int e0 = rowptr[i], e1 = rowptr[i + 1];
    float acc = 0.f;
    if (f < F) {
        for (int t = e0; t < e1; t++)
            acc += h[(size_t)csr_src[t] * F + f] * csr_w[t];
        float d = dinv[i];
        agg[(size_t)i * F + f] = acc + d * d * h[(size_t)i * F + f];
    }
}

// ---------------- tf32 tensor-core GEMM ----------------
__device__ __forceinline__ float to_tf32(float x) {
    float y;
    asm("cvt.rna.tf32.f32 %0, %1;" : "=f"(y) : "f"(x));
    return y;
}

__device__ __forceinline__ void mma_tf32(float& d0, float& d1, float& d2, float& d3,
                                         float a0, float a1, float a2, float a3,
                                         float b0, float b1) {
    asm("mma.sync.aligned.m16n8k8.row.col.f32.tf32.tf32.f32 "
        "{%0,%1,%2,%3},{%4,%5,%6,%7},{%8,%9},{%0,%1,%2,%3};"
        : "+f"(d0), "+f"(d1), "+f"(d2), "+f"(d3)
        : "r"(__float_as_uint(a0)), "r"(__float_as_uint(a1)),
          "r"(__float_as_uint(a2)), "r"(__float_as_uint(a3)),
          "r"(__float_as_uint(b0)), "r"(__float_as_uint(b1)));
}

// MODE 0: C = relu(A@B + bias), row-major.  MODE 1: dense-batch remap, no relu.
template <int MODE>
__global__ __launch_bounds__(256) void k_gemm_tc(const float* __restrict__ A,
                                                 const float* __restrict__ B,
                                                 const float* __restrict__ bias,
                                                 const void* __restrict__ batch,
                                                 const int* __restrict__ starts,
                                                 float* __restrict__ C,
                                                 int M, int K, int N, int max_num) {
    __shared__ float As[16][132];   // k-major: As[k][m]
    __shared__ float Bs[16][68];    // k-major: Bs[k][n]
    int tid = threadIdx.x;
    int warp = tid >> 5, lane = tid & 31;
    int wm = warp >> 2, wn = warp & 3;
    int gid = lane >> 2, t4 = lane & 3;
    int row0 = blockIdx.y * 128, col0 = blockIdx.x * 64;

    float acc[4][2][4];
    #pragma unroll
    for (int mt = 0; mt < 4; mt++)
        #pragma unroll
        for (int nt = 0; nt < 2; nt++)
            #pragma unroll
            for (int r = 0; r < 4; r++) acc[mt][nt][r] = 0.f;

    for (int kk = 0; kk < K; kk += 16) {
        {
            int r = tid >> 1;
            int kbase = (tid & 1) * 8;
            int grow = row0 + r;
            #pragma unroll
            for (int j = 0; j < 8; j++) {
                int gk = kk + kbase + j;
                float v = (grow < M && gk < K) ? A[(size_t)grow * K + gk] : 0.f;
                As[kbase + j][r] = to_tf32(v);
            }
        }
        #pragma unroll
        for (int rl = 0; rl < 4; rl++) {
            int idx = tid + rl * 256;
            int br = idx >> 6, bc = idx & 63;
            int gk = kk + br, gc = col0 + bc;
            float v = (gk < K && gc < N) ? B[(size_t)gk * N + gc] : 0.f;
            Bs[br][bc] = to_tf32(v);
        }
        __syncthreads();
        #pragma unroll
        for (int k8 = 0; k8 < 16; k8 += 8) {
            float bf[2][2];
            #pragma unroll
            for (int nt = 0; nt < 2; nt++) {
                int bc = wn * 16 + nt * 8 + gid;
                bf[nt][0] = Bs[k8 + t4][bc];
                bf[nt][1] = Bs[k8 + t4 + 4][bc];
            }
            #pragma unroll
            for (int mt = 0; mt < 4; mt++) {
                int ar = wm * 64 + mt * 16 + gid;
                float a0 = As[k8 + t4][ar];
                float a1 = As[k8 + t4][ar + 8];
                float a2 = As[k8 + t4 + 4][ar];
                float a3 = As[k8 + t4 + 4][ar + 8];
                #pragma unroll
                for (int nt = 0; nt < 2; nt++)
                    mma_tf32(acc[mt][nt][0], acc[mt][nt][1], acc[mt][nt][2], acc[mt][nt][3],
                             a0, a1, a2, a3, bf[nt][0], bf[nt][1]);
            }
        }
        __syncthreads();
    }

    int is64 = (MODE == 1) ? g_idx64 : 0;
    #pragma unroll
    for (int mt = 0; mt < 4; mt++) {
        #pragma unroll
        for (int half = 0; half < 2; half++) {
            int row = row0 + wm * 64 + mt * 16 + gid + half * 8;
            if (row >= M) continue;
            float* orow;
            if (MODE == 0) {
                orow = C + (size_t)row * N;
            } else {
                int bg = idx_at(batch, row, is64);
                int pos = row - starts[bg];
                if (pos >= max_num) continue;
                orow = C + ((size_t)bg * max_num + pos) * N;
            }
            #pragma unroll
            for (int nt = 0; nt < 2; nt++) {
                int col = col0 + wn * 16 + nt * 8 + t4 * 2;
                #pragma unroll
                for (int c = 0; c < 2; c++) {
                    if (col + c < N) {
                        float v = acc[mt][nt][half * 2 + c] + bias[col + c];
                        if (MODE == 0) v = fmaxf(v, 0.f);
                        orow[col + c] = v;
                    }
                }
            }
        }
    }
}

// ---------------- aggregation dispatch helper ----------------
static void launch_agg(const float* h, const int* rowptr, const int* csr_src,
                       const float* csr_w, const float* dinv, float* agg,
                       int Nn, int F) {
    if (F == 54) {
        int gpb = 256 / 32;
        k_agg_w<27, 32><<<(Nn + gpb - 1) / gpb, 256>>>(
            (const float2*)h, rowptr, csr_src, csr_w, dinv, (float2*)agg, Nn);
    } else if (F == 108) {
        int gpb = 256 / 64;
        k_agg_w<54, 64><<<(Nn + gpb - 1) / gpb, 256>>>(
            (const float2*)h, rowptr, csr_src, csr_w, dinv, (float2*)agg, Nn);
    } else {
        int bt = ((F + 31) / 32) * 32;
        k_aggregate<<<Nn, bt>>>(h, rowptr, csr_src, csr_w, dinv, agg, F);
    }
}

// ---------------- host launcher ----------------
extern "C" void kernel_launch(void* const* d_in, const int* in_sizes, int n_in,
                              void* d_out, int out_size) {
    const float* x     = (const float*)d_in[0];
    const void*  ei    = d_in[1];
    const void*  batch = d_in[2];
    const float* W1 = (const float*)d_in[4];
    const float* b1 = (const float*)d_in[5];
    const float* W2 = (const float*)d_in[6];
    const float* b2 = (const float*)d_in[7];
    const float* W3 = (const float*)d_in[8];
    const float* b3 = (const float*)d_in[9];
    const float* Wf = (const float*)d_in[10];
    const float* bf = (const float*)d_in[11];
    float* out = (float*)d_out;

    int N  = in_sizes[2];            // nodes
    int E  = in_sizes[1] / 2;        // edges
    int F0 = in_sizes[0] / N;        // 54
    int F2 = in_sizes[6] / F0;       // 108
    int F3 = in_sizes[8] / F2;       // 216
    int FO = in_sizes[10] / F3;      // 200
    int max_num = out_size / (NGRAPHS * FO);

    float *p_h, *p_agg, *p_dinv, *p_csr_w;
    int *p_cnt, *p_rowptr, *p_cursor, *p_csr_src, *p_starts;
    cudaGetSymbolAddress((void**)&p_h, g_h);
    cudaGetSymbolAddress((void**)&p_agg, g_agg);
    cudaGetSymbolAddress((void**)&p_dinv, g_dinv);
    cudaGetSymbolAddress((void**)&p_cnt, g_cnt);
    cudaGetSymbolAddress((void**)&p_rowptr, g_rowptr);
    cudaGetSymbolAddress((void**)&p_cursor, g_cursor);
    cudaGetSymbolAddress((void**)&p_csr_src, g_csr_src);
    cudaGetSymbolAddress((void**)&p_csr_w, g_csr_w);
    cudaGetSymbolAddress((void**)&p_starts, g_starts);

    const int T = 256;
    int nb_n = (N + T - 1) / T;
    int nb_e = (E + T - 1) / T;

    k_detect<<<1, 32>>>((const int*)ei);
    k_starts<<<1, NGRAPHS>>>(batch, N, p_starts);
    {
        dim3 zgrid(32, NGRAPHS);
        k_zero_tail<<<zgrid, T>>>((float4*)out, p_starts, max_num, FO, N);
    }

    // CSR build + normalization
    k_zero_i<<<nb_n, T>>>(p_cnt, N);
    k_count<<<nb_e, T>>>(ei, p_cnt, E, N);
    k_scan<<<1, 1024>>>(p_cnt, p_rowptr, p_cursor, p_dinv, N);
    k_fill<<<nb_e, T>>>(ei, p_dinv, p_cursor, p_csr_src, p_csr_w, E, N);

    int mb = (N + 127) / 128;

    // ---- layer 1: agg(x) @ W1 + b1, relu ----
    launch_agg(x, p_rowptr, p_csr_src, p_csr_w, p_dinv, p_agg, N, F0);
    {
        dim3 grid((F0 + 63) / 64, mb);
        k_gemm_tc<0><<<grid, T>>>(p_agg, W1, b1, nullptr, nullptr, p_h, N, F0, F0, 0);
    }
    // ---- layer 2: agg(h1) @ W2 + b2, relu ----
    launch_agg(p_h, p_rowptr, p_csr_src, p_csr_w, p_dinv, p_agg, N, F0);
    {
        dim3 grid((F2 + 63) / 64, mb);
        k_gemm_tc<0><<<grid, T>>>(p_agg, W2, b2, nullptr, nullptr, p_h, N, F0, F2, 0);
    }
    // ---- layer 3: agg(h2) @ W3 + b3, relu ----
    launch_agg(p_h, p_rowptr, p_csr_src, p_csr_w, p_dinv, p_agg, N, F2);
    {
        dim3 grid((F3 + 63) / 64, mb);
        k_gemm_tc<0><<<grid, T>>>(p_agg, W3, b3, nullptr, nullptr, p_h, N, F2, F3, 0);
    }
    // ---- final: h3 @ Wf + bf -> dense [64, max_num, FO] ----
    {
        dim3 grid((FO + 63) / 64, mb);
        k_gemm_tc<1><<<grid, T>>>(p_h, Wf, bf, batch, p_starts, out,
                                  N, F3, FO, max_num);
    }
}